// round 7
// baseline (speedup 1.0000x reference)
#include <cuda_runtime.h>
#include <cstdint>

#define N 4096
#define D 128
#define BHALF 2048
#define INV_T 14.285714285714285714f  /* 1/0.07 */

// ---------------- scratch (static device globals; no allocation) ----------------
__device__ __align__(16) float    g_f[N * D];      // L2-normalized features, fp32
__device__ __align__(16) unsigned g_ftf[N * D];    // tf32-rounded copies (bit pattern)
__device__ int    g_cnt[N];
__device__ int    g_sidx[N * 64];
__device__ float  g_sval[N * 64];
__device__ float  g_partial[N * 32];               // [row][slot] coalesced for rowfix
__device__ float  g_lp[N];
__device__ int    g_done;                          // zero-init; reset by last block each call

// ---------------- K1: fused L2-norm (warp 0) + row-wise sparsemax ----------------
#define CAND_MAX 128

__global__ void __launch_bounds__(512) k_sparse(const float* __restrict__ feat,
                                                const float* __restrict__ attn,
                                                float* __restrict__ outm) {
    const int i = blockIdx.x;
    const int tid = threadIdx.x;
    __shared__ float wred[16];
    __shared__ int   wcnt[16];
    __shared__ float s_max, s_tau;
    __shared__ int   s_ccnt, s_fb;
    __shared__ int   s_cidx[CAND_MAX];
    __shared__ float s_cval[CAND_MAX];

    // norm prologue: warp 0 normalizes feature row i (no cross-warp dependency)
    if (tid < 32) {
        float4 v = *(const float4*)(feat + (size_t)i * D + tid * 4);
        float s = v.x * v.x + v.y * v.y + v.z * v.z + v.w * v.w;
        #pragma unroll
        for (int o = 16; o; o >>= 1) s += __shfl_xor_sync(0xffffffffu, s, o);
        float r = sqrtf(s);
        float4 f = make_float4(v.x / r, v.y / r, v.z / r, v.w / r);
        *(float4*)(g_f + (size_t)i * D + tid * 4) = f;
        uint4 tf;
        asm("cvt.rna.tf32.f32 %0, %1;" : "=r"(tf.x) : "f"(f.x));
        asm("cvt.rna.tf32.f32 %0, %1;" : "=r"(tf.y) : "f"(f.y));
        asm("cvt.rna.tf32.f32 %0, %1;" : "=r"(tf.z) : "f"(f.z));
        asm("cvt.rna.tf32.f32 %0, %1;" : "=r"(tf.w) : "f"(f.w));
        *(uint4*)(g_ftf + (size_t)i * D + tid * 4) = tf;
    }

    const int j1 = i & (BHALF - 1);
    const int j2 = j1 + BHALF;
    const float4* row4 = (const float4*)(attn + (size_t)i * N);

    // pass A: vectorized load, scale, mask positives/diag, track max
    float z[8];
    float mx = -3.402823466e38f;
    #pragma unroll
    for (int it = 0; it < 2; it++) {
        int v = tid + it * 512;            // float4 index 0..1023
        float4 r = row4[v];
        int j = v * 4;
        float z0 = (j     == j1 || j     == j2) ? 0.f : r.x * INV_T;
        float z1 = (j + 1 == j1 || j + 1 == j2) ? 0.f : r.y * INV_T;
        float z2 = (j + 2 == j1 || j + 2 == j2) ? 0.f : r.z * INV_T;
        float z3 = (j + 3 == j1 || j + 3 == j2) ? 0.f : r.w * INV_T;
        z[it * 4] = z0; z[it * 4 + 1] = z1; z[it * 4 + 2] = z2; z[it * 4 + 3] = z3;
        mx = fmaxf(mx, fmaxf(fmaxf(z0, z1), fmaxf(z2, z3)));
    }
    #pragma unroll
    for (int o = 16; o; o >>= 1) mx = fmaxf(mx, __shfl_xor_sync(0xffffffffu, mx, o));
    if ((tid & 31) == 0) wred[tid >> 5] = mx;
    if (tid == 0) s_ccnt = 0;
    __syncthreads();
    if (tid == 0) {
        float m = wred[0];
        for (int w = 1; w < 16; w++) m = fmaxf(m, wred[w]);
        s_max = m;
    }
    __syncthreads();

    // pass B: gather candidates z >= max - 1 (sparsemax support bound)
    const float thr = s_max - 1.0f;
    #pragma unroll
    for (int it = 0; it < 2; it++) {
        int j = (tid + it * 512) * 4;
        #pragma unroll
        for (int q = 0; q < 4; q++) {
            float v = z[it * 4 + q];
            if (v >= thr) {
                int p = atomicAdd(&s_ccnt, 1);
                if (p < CAND_MAX) { s_cidx[p] = j + q; s_cval[p] = v; }
            }
        }
    }
    __syncthreads();

    if (tid == 0) {
        int cnt = s_ccnt;
        s_fb = (cnt > CAND_MAX);
        if (!s_fb) {
            // insertion sort desc by (value, index asc) -> deterministic
            for (int a = 1; a < cnt; a++) {
                float v = s_cval[a]; int ix = s_cidx[a];
                int b = a - 1;
                while (b >= 0 && (s_cval[b] < v || (s_cval[b] == v && s_cidx[b] > ix))) {
                    s_cval[b + 1] = s_cval[b]; s_cidx[b + 1] = s_cidx[b]; b--;
                }
                s_cval[b + 1] = v; s_cidx[b + 1] = ix;
            }
            // reference formula: fp32 sequential cumsum over descending values
            float cum = 0.f, cumkz = 1.f; int kz = 1;
            for (int k = 1; k <= cnt; k++) {
                float v = s_cval[k - 1];
                cum += v;
                if (1.0f + (float)k * v > cum) { kz = k; cumkz = cum; }
            }
            float tau = (cumkz - 1.0f) / (float)kz;
            s_tau = tau;
            g_cnt[i] = kz;
            int lim = kz < 64 ? kz : 64;
            for (int k = 0; k < lim; k++) {
                g_sidx[i * 64 + k] = s_cidx[k];
                g_sval[i * 64 + k] = s_cval[k] - tau;
            }
        }
    }
    __syncthreads();

    if (s_fb) {
        // fp32 Michelot fallback (safety only)
        float tau = -3.402823466e38f;
        for (int iter = 0; iter < 64; iter++) {
            float s = 0.f; int c = 0;
            #pragma unroll
            for (int it = 0; it < 8; it++) {
                float v = z[it];
                if (v > tau) { s += v; c++; }
            }
            #pragma unroll
            for (int o = 16; o; o >>= 1) {
                s += __shfl_xor_sync(0xffffffffu, s, o);
                c += __shfl_xor_sync(0xffffffffu, c, o);
            }
            if ((tid & 31) == 0) { wred[tid >> 5] = s; wcnt[tid >> 5] = c; }
            __syncthreads();
            if (tid == 0) {
                float S = 0.f; int C = 0;
                for (int w = 0; w < 16; w++) { S += wred[w]; C += wcnt[w]; }
                s_tau = (S - 1.0f) / (float)C;
            }
            __syncthreads();
            float tn = s_tau;
            if (tn == tau) break;
            tau = tn;
            __syncthreads();
        }
        if (tid == 0) g_cnt[i] = N;
        __syncthreads();
    }

    // pass C: write masked row (4 STG.32 rounds within 512B windows; L2 merges)
    const float tau = s_tau;
    float* orow = outm + (size_t)i * N;
    #pragma unroll
    for (int it = 0; it < 2; it++) {
        int j = (tid + it * 512) * 4;
        orow[j]     = fmaxf(z[it * 4]     - tau, 0.f);
        orow[j + 1] = fmaxf(z[it * 4 + 1] - tau, 0.f);
        orow[j + 2] = fmaxf(z[it * 4 + 2] - tau, 0.f);
        orow[j + 3] = fmaxf(z[it * 4 + 3] - tau, 0.f);
    }
}

// ---------------- K2: symmetric tf32 Gram + exp + row/col partial sums ----------------
__device__ __forceinline__ void mma_tf32(float c[4], const unsigned a[4], const unsigned b[2]) {
    asm volatile(
        "mma.sync.aligned.m16n8k8.row.col.f32.tf32.tf32.f32 "
        "{%0,%1,%2,%3}, {%4,%5,%6,%7}, {%8,%9}, {%0,%1,%2,%3};\n"
        : "+f"(c[0]), "+f"(c[1]), "+f"(c[2]), "+f"(c[3])
        : "r"(a[0]), "r"(a[1]), "r"(a[2]), "r"(a[3]), "r"(b[0]), "r"(b[1]));
}

#define LDA 36

__global__ void __launch_bounds__(256) k_gemm() {
    int t = blockIdx.x, bi = 0;
    while (t >= 32 - bi) { t -= 32 - bi; bi++; }
    const int bj = bi + t;
    const bool diag = (bi == bj);

    __shared__ __align__(16) unsigned As[128 * LDA];
    __shared__ __align__(16) unsigned Bs[128 * LDA];
    __shared__ float sZr[128];
    __shared__ float sZc[4][128];

    const int tid = threadIdx.x;
    const int lane = tid & 31, wid = tid >> 5;
    const int wm = wid >> 1, wn = wid & 1;
    const int g = lane >> 2, t4 = lane & 3;

    if (tid < 128) sZr[tid] = 0.0f;

    float acc[2][8][4];
    #pragma unroll
    for (int mt = 0; mt < 2; mt++)
        #pragma unroll
        for (int nt = 0; nt < 8; nt++)
            #pragma unroll
            for (int k = 0; k < 4; k++) acc[mt][nt][k] = 0.0f;

    const int lr = tid >> 1;
    const int lh = tid & 1;
    const unsigned* Bp = diag ? As : Bs;

    for (int kc = 0; kc < 4; kc++) {
        #pragma unroll
        for (int q = 0; q < 4; q++) {
            int cv = lh * 4 + q;
            uint4 va = *(const uint4*)(g_ftf + ((size_t)(bi * 128 + lr) * D + kc * 32 + cv * 4));
            *(uint4*)(As + lr * LDA + cv * 4) = va;
            if (!diag) {
                uint4 vb = *(const uint4*)(g_ftf + ((size_t)(bj * 128 + lr) * D + kc * 32 + cv * 4));
                *(uint4*)(Bs + lr * LDA + cv * 4) = vb;
            }
        }
        __syncthreads();

        #pragma unroll
        for (int ks = 0; ks < 4; ks++) {
            unsigned a[2][4], b[8][2];
            #pragma unroll
            for (int mt = 0; mt < 2; mt++) {
                int r0 = wm * 32 + mt * 16 + g;
                a[mt][0] = As[r0 * LDA + ks * 8 + t4];
                a[mt][1] = As[(r0 + 8) * LDA + ks * 8 + t4];
                a[mt][2] = As[r0 * LDA + ks * 8 + t4 + 4];
                a[mt][3] = As[(r0 + 8) * LDA + ks * 8 + t4 + 4];
            }
            #pragma unroll
            for (int nt = 0; nt < 8; nt++) {
                int c0 = wn * 64 + nt * 8 + g;
                b[nt][0] = Bp[c0 * LDA + ks * 8 + t4];
                b[nt][1] = Bp[c0 * LDA + ks * 8 + t4 + 4];
            }
            #pragma unroll
            for (int mt = 0; mt < 2; mt++)
                #pragma unroll
                for (int nt = 0; nt < 8; nt++) mma_tf32(acc[mt][nt], a[mt], b[nt]);
        }
        __syncthreads();
    }

    const int ibase = bi * 128, jbase = bj * 128;
    float cp0[8], cp1[8];
    #pragma unroll
    for (int nt = 0; nt < 8; nt++) { cp0[nt] = 0.f; cp1[nt] = 0.f; }

    #pragma unroll
    for (int mt = 0; mt < 2; mt++) {
        int r0 = wm * 32 + mt * 16 + g;
        int gi0 = ibase + r0, gi1 = gi0 + 8;
        float rs0 = 0.f, rs1 = 0.f;
        #pragma unroll
        for (int nt = 0; nt < 8; nt++) {
            int c0 = wn * 64 + nt * 8 + t4 * 2;
            int gj0 = jbase + c0, gj1 = gj0 + 1;
            float e0 = __expf((acc[mt][nt][0] - 1.0f) * INV_T);
            float e1 = __expf((acc[mt][nt][1] - 1.0f) * INV_T);
            float e2 = __expf((acc[mt][nt][2] - 1.0f) * INV_T);
            float e3 = __expf((acc[mt][nt][3] - 1.0f) * INV_T);
            if (diag) {
                if (gj0 == gi0) e0 = 0.f;
                if (gj1 == gi0) e1 = 0.f;
                if (gj0 == gi1) e2 = 0.f;
                if (gj1 == gi1) e3 = 0.f;
            }
            rs0 += e0 + e1; rs1 += e2 + e3;
            cp0[nt] += e0 + e2; cp1[nt] += e1 + e3;
        }
        rs0 += __shfl_xor_sync(0xffffffffu, rs0, 1);
        rs0 += __shfl_xor_sync(0xffffffffu, rs0, 2);
        rs1 += __shfl_xor_sync(0xffffffffu, rs1, 1);
        rs1 += __shfl_xor_sync(0xffffffffu, rs1, 2);
        if (t4 == 0) {
            atomicAdd(&sZr[r0], rs0);
            atomicAdd(&sZr[r0 + 8], rs1);
        }
    }

    if (!diag) {
        #pragma unroll
        for (int nt = 0; nt < 8; nt++) {
            #pragma unroll
            for (int o = 4; o <= 16; o <<= 1) {
                cp0[nt] += __shfl_xor_sync(0xffffffffu, cp0[nt], o);
                cp1[nt] += __shfl_xor_sync(0xffffffffu, cp1[nt], o);
            }
        }
        if (g == 0) {
            #pragma unroll
            for (int nt = 0; nt < 8; nt++) {
                int c = wn * 64 + nt * 8 + t4 * 2;
                sZc[wm][c] = cp0[nt];
                sZc[wm][c + 1] = cp1[nt];
            }
        }
    }
    __syncthreads();

    if (tid < 128) {
        g_partial[(size_t)(ibase + tid) * 32 + bj] = sZr[tid];
        if (!diag) {
            float cs = ((sZc[0][tid] + sZc[1][tid]) + sZc[2][tid]) + sZc[3][tid];
            g_partial[(size_t)(jbase + tid) * 32 + bi] = cs;
        }
    }
}

// ---------------- K3: per-row log-prob (warp per row) + fused final loss ----------------
__global__ void __launch_bounds__(256) k_rowfix(const float* __restrict__ outm,
                                                float* __restrict__ out, int moff) {
    const int wid = threadIdx.x >> 5, lane = threadIdx.x & 31;
    const int i = blockIdx.x * 8 + wid;

    const float4 a = *(const float4*)(g_f + (size_t)i * D + lane * 4);

    auto dot = [&](int j) -> float {
        float4 b = *(const float4*)(g_f + (size_t)j * D + lane * 4);
        float p = a.x * b.x + a.y * b.y + a.z * b.z + a.w * b.w;
        #pragma unroll
        for (int o = 16; o; o >>= 1) p += __shfl_xor_sync(0xffffffffu, p, o);
        return p;
    };

    float simpos = (dot(i ^ BHALF) - 1.0f) * INV_T;

    int cnt = g_cnt[i];
    float corr = 0.0f;
    if (cnt <= 64) {
        for (int k = 0; k < cnt; k++) {
            int j = g_sidx[i * 64 + k];
            float m = g_sval[i * 64 + k];
            corr += m * __expf((dot(j) - 1.0f) * INV_T);
        }
    } else {
        for (int j = 0; j < N; j++) {
            float m = outm[(size_t)i * N + j];
            if (m > 0.0f) corr += m * __expf((dot(j) - 1.0f) * INV_T);
        }
    }

    float zp = g_partial[(size_t)i * 32 + lane];   // one coalesced 128B line per warp
    #pragma unroll
    for (int o = 16; o; o >>= 1) zp += __shfl_xor_sync(0xffffffffu, zp, o);

    if (lane == 0) g_lp[i] = simpos - logf(zp - corr);

    // ---- last-block loss reduction (threadFenceReduction pattern; deterministic order) ----
    __syncthreads();
    __shared__ bool isLast;
    if (threadIdx.x == 0) {
        __threadfence();
        int prev = atomicAdd(&g_done, 1);
        isLast = (prev == (int)gridDim.x - 1);
    }
    __syncthreads();
    if (isLast) {
        __shared__ float sm[8];
        float s = 0.0f;
        #pragma unroll
        for (int k = 0; k < 16; k++) s += g_lp[threadIdx.x + k * 256];
        #pragma unroll
        for (int o = 16; o; o >>= 1) s += __shfl_xor_sync(0xffffffffu, s, o);
        if (lane == 0) sm[wid] = s;
        __syncthreads();
        if (threadIdx.x == 0) {
            float tot = ((sm[0] + sm[1]) + (sm[2] + sm[3])) + ((sm[4] + sm[5]) + (sm[6] + sm[7]));
            float loss = -(tot / 4096.0f);
            for (int q = 0; q < moff; q++) out[q] = loss;
            g_done = 0;   // reset for next graph replay
        }
    }
}

// ---------------- launch ----------------
extern "C" void kernel_launch(void* const* d_in, const int* in_sizes, int n_in,
                              void* d_out, int out_size) {
    int fidx = (in_sizes[0] == N * D) ? 0 : 1;
    const float* feat = (const float*)d_in[fidx];
    const float* attn = (const float*)d_in[1 - fidx];
    float* out = (float*)d_out;

    long long nn = (long long)N * (long long)N;
    int moff = (int)((long long)out_size - nn);
    if (moff < 0) moff = 0;
    float* outm = out + moff;

    k_sparse<<<N, 512>>>(feat, attn, outm);
    k_gemm<<<528, 256>>>();
    k_rowfix<<<512, 256>>>(outm, out, moff);
}

// round 8
// speedup vs baseline: 1.1071x; 1.1071x over previous
#include <cuda_runtime.h>
#include <cstdint>

#define N 4096
#define D 128
#define BHALF 2048
#define INV_T 14.285714285714285714f  /* 1/0.07 */

// ---------------- scratch (static device globals; no allocation) ----------------
__device__ __align__(16) float    g_f[N * D];      // L2-normalized features, fp32
__device__ __align__(16) unsigned g_ftf[N * D];    // tf32-rounded copies (bit pattern)
__device__ int    g_cnt[N];
__device__ int    g_sidx[N * 64];
__device__ float  g_sval[N * 64];
__device__ float  g_partial[N * 32];               // [row][slot] coalesced for rowfix
__device__ float  g_lp[N];
__device__ int    g_done;                          // zero-init; reset by last block each call

// ---------------- K1: fused L2-norm (warp 0) + row-wise sparsemax ----------------
#define CAND_MAX 128

__global__ void __launch_bounds__(512) k_sparse(const float* __restrict__ feat,
                                                const float* __restrict__ attn,
                                                float* __restrict__ outm) {
    const int i = blockIdx.x;
    const int tid = threadIdx.x;
    __shared__ __align__(16) float zs[N];          // staging for coalesced stores
    __shared__ float wred[16];
    __shared__ int   wcnt[16];
    __shared__ float s_max, s_tau;
    __shared__ int   s_ccnt, s_fb;
    __shared__ int   s_cidx[CAND_MAX];
    __shared__ float s_cval[CAND_MAX];

    // norm prologue: warp 0 normalizes feature row i (no cross-warp dependency)
    if (tid < 32) {
        float4 v = *(const float4*)(feat + (size_t)i * D + tid * 4);
        float s = v.x * v.x + v.y * v.y + v.z * v.z + v.w * v.w;
        #pragma unroll
        for (int o = 16; o; o >>= 1) s += __shfl_xor_sync(0xffffffffu, s, o);
        float r = sqrtf(s);
        float4 f = make_float4(v.x / r, v.y / r, v.z / r, v.w / r);
        *(float4*)(g_f + (size_t)i * D + tid * 4) = f;
        uint4 tf;
        asm("cvt.rna.tf32.f32 %0, %1;" : "=r"(tf.x) : "f"(f.x));
        asm("cvt.rna.tf32.f32 %0, %1;" : "=r"(tf.y) : "f"(f.y));
        asm("cvt.rna.tf32.f32 %0, %1;" : "=r"(tf.z) : "f"(f.z));
        asm("cvt.rna.tf32.f32 %0, %1;" : "=r"(tf.w) : "f"(f.w));
        *(uint4*)(g_ftf + (size_t)i * D + tid * 4) = tf;
    }

    const int j1 = i & (BHALF - 1);
    const int j2 = j1 + BHALF;
    const float4* row4 = (const float4*)(attn + (size_t)i * N);

    // pass A: vectorized load, scale, mask positives/diag, track max
    float z[8];
    float mx = -3.402823466e38f;
    #pragma unroll
    for (int it = 0; it < 2; it++) {
        int v = tid + it * 512;            // float4 index 0..1023
        float4 r = row4[v];
        int j = v * 4;
        float z0 = (j     == j1 || j     == j2) ? 0.f : r.x * INV_T;
        float z1 = (j + 1 == j1 || j + 1 == j2) ? 0.f : r.y * INV_T;
        float z2 = (j + 2 == j1 || j + 2 == j2) ? 0.f : r.z * INV_T;
        float z3 = (j + 3 == j1 || j + 3 == j2) ? 0.f : r.w * INV_T;
        z[it * 4] = z0; z[it * 4 + 1] = z1; z[it * 4 + 2] = z2; z[it * 4 + 3] = z3;
        mx = fmaxf(mx, fmaxf(fmaxf(z0, z1), fmaxf(z2, z3)));
    }
    #pragma unroll
    for (int o = 16; o; o >>= 1) mx = fmaxf(mx, __shfl_xor_sync(0xffffffffu, mx, o));
    if ((tid & 31) == 0) wred[tid >> 5] = mx;
    if (tid == 0) s_ccnt = 0;
    __syncthreads();
    if (tid == 0) {
        float m = wred[0];
        for (int w = 1; w < 16; w++) m = fmaxf(m, wred[w]);
        s_max = m;
    }
    __syncthreads();

    // pass B: gather candidates z >= max - 1 (sparsemax support bound)
    const float thr = s_max - 1.0f;
    #pragma unroll
    for (int it = 0; it < 2; it++) {
        int j = (tid + it * 512) * 4;
        #pragma unroll
        for (int q = 0; q < 4; q++) {
            float v = z[it * 4 + q];
            if (v >= thr) {
                int p = atomicAdd(&s_ccnt, 1);
                if (p < CAND_MAX) { s_cidx[p] = j + q; s_cval[p] = v; }
            }
        }
    }
    __syncthreads();

    if (tid == 0) {
        int cnt = s_ccnt;
        s_fb = (cnt > CAND_MAX);
        if (!s_fb) {
            // insertion sort desc by (value, index asc) -> deterministic
            for (int a = 1; a < cnt; a++) {
                float v = s_cval[a]; int ix = s_cidx[a];
                int b = a - 1;
                while (b >= 0 && (s_cval[b] < v || (s_cval[b] == v && s_cidx[b] > ix))) {
                    s_cval[b + 1] = s_cval[b]; s_cidx[b + 1] = s_cidx[b]; b--;
                }
                s_cval[b + 1] = v; s_cidx[b + 1] = ix;
            }
            // reference formula: fp32 sequential cumsum over descending values
            float cum = 0.f, cumkz = 1.f; int kz = 1;
            for (int k = 1; k <= cnt; k++) {
                float v = s_cval[k - 1];
                cum += v;
                if (1.0f + (float)k * v > cum) { kz = k; cumkz = cum; }
            }
            float tau = (cumkz - 1.0f) / (float)kz;
            s_tau = tau;
            g_cnt[i] = kz;
            int lim = kz < 64 ? kz : 64;
            for (int k = 0; k < lim; k++) {
                g_sidx[i * 64 + k] = s_cidx[k];
                g_sval[i * 64 + k] = s_cval[k] - tau;
            }
        }
    }
    __syncthreads();

    if (s_fb) {
        // fp32 Michelot fallback (safety only)
        float tau = -3.402823466e38f;
        for (int iter = 0; iter < 64; iter++) {
            float s = 0.f; int c = 0;
            #pragma unroll
            for (int it = 0; it < 8; it++) {
                float v = z[it];
                if (v > tau) { s += v; c++; }
            }
            #pragma unroll
            for (int o = 16; o; o >>= 1) {
                s += __shfl_xor_sync(0xffffffffu, s, o);
                c += __shfl_xor_sync(0xffffffffu, c, o);
            }
            if ((tid & 31) == 0) { wred[tid >> 5] = s; wcnt[tid >> 5] = c; }
            __syncthreads();
            if (tid == 0) {
                float S = 0.f; int C = 0;
                for (int w = 0; w < 16; w++) { S += wred[w]; C += wcnt[w]; }
                s_tau = (S - 1.0f) / (float)C;
            }
            __syncthreads();
            float tn = s_tau;
            if (tn == tau) break;
            tau = tn;
            __syncthreads();
        }
        if (tid == 0) g_cnt[i] = N;
        __syncthreads();
    }

    // pass C: registers -> smem (float4 layout, conflict-free) -> coalesced scalar STG
    const float tau = s_tau;
    #pragma unroll
    for (int it = 0; it < 2; it++) {
        int v = tid + it * 512;
        float4 m;
        m.x = fmaxf(z[it * 4]     - tau, 0.f);
        m.y = fmaxf(z[it * 4 + 1] - tau, 0.f);
        m.z = fmaxf(z[it * 4 + 2] - tau, 0.f);
        m.w = fmaxf(z[it * 4 + 3] - tau, 0.f);
        *(float4*)(zs + v * 4) = m;
    }
    __syncthreads();
    float* orow = outm + (size_t)i * N;
    #pragma unroll
    for (int it = 0; it < 8; it++) {
        int j = tid + it * 512;
        orow[j] = zs[j];       // 1 L1 wavefront per STG.32 (128B contiguous per warp)
    }
}

// ---------------- K2: symmetric tf32 Gram + exp + row/col partial sums ----------------
__device__ __forceinline__ void mma_tf32(float c[4], const unsigned a[4], const unsigned b[2]) {
    asm volatile(
        "mma.sync.aligned.m16n8k8.row.col.f32.tf32.tf32.f32 "
        "{%0,%1,%2,%3}, {%4,%5,%6,%7}, {%8,%9}, {%0,%1,%2,%3};\n"
        : "+f"(c[0]), "+f"(c[1]), "+f"(c[2]), "+f"(c[3])
        : "r"(a[0]), "r"(a[1]), "r"(a[2]), "r"(a[3]), "r"(b[0]), "r"(b[1]));
}

#define LDA 36

__global__ void __launch_bounds__(256) k_gemm() {
    int t = blockIdx.x, bi = 0;
    while (t >= 32 - bi) { t -= 32 - bi; bi++; }
    const int bj = bi + t;
    const bool diag = (bi == bj);

    __shared__ __align__(16) unsigned As[128 * LDA];
    __shared__ __align__(16) unsigned Bs[128 * LDA];
    __shared__ float sZr[128];
    __shared__ float sZc[4][128];

    const int tid = threadIdx.x;
    const int lane = tid & 31, wid = tid >> 5;
    const int wm = wid >> 1, wn = wid & 1;
    const int g = lane >> 2, t4 = lane & 3;

    if (tid < 128) sZr[tid] = 0.0f;

    float acc[2][8][4];
    #pragma unroll
    for (int mt = 0; mt < 2; mt++)
        #pragma unroll
        for (int nt = 0; nt < 8; nt++)
            #pragma unroll
            for (int k = 0; k < 4; k++) acc[mt][nt][k] = 0.0f;

    const int lr = tid >> 1;
    const int lh = tid & 1;
    const unsigned* Bp = diag ? As : Bs;

    for (int kc = 0; kc < 4; kc++) {
        #pragma unroll
        for (int q = 0; q < 4; q++) {
            int cv = lh * 4 + q;
            uint4 va = *(const uint4*)(g_ftf + ((size_t)(bi * 128 + lr) * D + kc * 32 + cv * 4));
            *(uint4*)(As + lr * LDA + cv * 4) = va;
            if (!diag) {
                uint4 vb = *(const uint4*)(g_ftf + ((size_t)(bj * 128 + lr) * D + kc * 32 + cv * 4));
                *(uint4*)(Bs + lr * LDA + cv * 4) = vb;
            }
        }
        __syncthreads();

        #pragma unroll
        for (int ks = 0; ks < 4; ks++) {
            unsigned a[2][4], b[8][2];
            #pragma unroll
            for (int mt = 0; mt < 2; mt++) {
                int r0 = wm * 32 + mt * 16 + g;
                a[mt][0] = As[r0 * LDA + ks * 8 + t4];
                a[mt][1] = As[(r0 + 8) * LDA + ks * 8 + t4];
                a[mt][2] = As[r0 * LDA + ks * 8 + t4 + 4];
                a[mt][3] = As[(r0 + 8) * LDA + ks * 8 + t4 + 4];
            }
            #pragma unroll
            for (int nt = 0; nt < 8; nt++) {
                int c0 = wn * 64 + nt * 8 + g;
                b[nt][0] = Bp[c0 * LDA + ks * 8 + t4];
                b[nt][1] = Bp[c0 * LDA + ks * 8 + t4 + 4];
            }
            #pragma unroll
            for (int mt = 0; mt < 2; mt++)
                #pragma unroll
                for (int nt = 0; nt < 8; nt++) mma_tf32(acc[mt][nt], a[mt], b[nt]);
        }
        __syncthreads();
    }

    const int ibase = bi * 128, jbase = bj * 128;
    float cp0[8], cp1[8];
    #pragma unroll
    for (int nt = 0; nt < 8; nt++) { cp0[nt] = 0.f; cp1[nt] = 0.f; }

    #pragma unroll
    for (int mt = 0; mt < 2; mt++) {
        int r0 = wm * 32 + mt * 16 + g;
        int gi0 = ibase + r0, gi1 = gi0 + 8;
        float rs0 = 0.f, rs1 = 0.f;
        #pragma unroll
        for (int nt = 0; nt < 8; nt++) {
            int c0 = wn * 64 + nt * 8 + t4 * 2;
            int gj0 = jbase + c0, gj1 = gj0 + 1;
            float e0 = __expf((acc[mt][nt][0] - 1.0f) * INV_T);
            float e1 = __expf((acc[mt][nt][1] - 1.0f) * INV_T);
            float e2 = __expf((acc[mt][nt][2] - 1.0f) * INV_T);
            float e3 = __expf((acc[mt][nt][3] - 1.0f) * INV_T);
            if (diag) {
                if (gj0 == gi0) e0 = 0.f;
                if (gj1 == gi0) e1 = 0.f;
                if (gj0 == gi1) e2 = 0.f;
                if (gj1 == gi1) e3 = 0.f;
            }
            rs0 += e0 + e1; rs1 += e2 + e3;
            cp0[nt] += e0 + e2; cp1[nt] += e1 + e3;
        }
        rs0 += __shfl_xor_sync(0xffffffffu, rs0, 1);
        rs0 += __shfl_xor_sync(0xffffffffu, rs0, 2);
        rs1 += __shfl_xor_sync(0xffffffffu, rs1, 1);
        rs1 += __shfl_xor_sync(0xffffffffu, rs1, 2);
        if (t4 == 0) {
            atomicAdd(&sZr[r0], rs0);
            atomicAdd(&sZr[r0 + 8], rs1);
        }
    }

    if (!diag) {
        #pragma unroll
        for (int nt = 0; nt < 8; nt++) {
            #pragma unroll
            for (int o = 4; o <= 16; o <<= 1) {
                cp0[nt] += __shfl_xor_sync(0xffffffffu, cp0[nt], o);
                cp1[nt] += __shfl_xor_sync(0xffffffffu, cp1[nt], o);
            }
        }
        if (g == 0) {
            #pragma unroll
            for (int nt = 0; nt < 8; nt++) {
                int c = wn * 64 + nt * 8 + t4 * 2;
                sZc[wm][c] = cp0[nt];
                sZc[wm][c + 1] = cp1[nt];
            }
        }
    }
    __syncthreads();

    if (tid < 128) {
        g_partial[(size_t)(ibase + tid) * 32 + bj] = sZr[tid];
        if (!diag) {
            float cs = ((sZc[0][tid] + sZc[1][tid]) + sZc[2][tid]) + sZc[3][tid];
            g_partial[(size_t)(jbase + tid) * 32 + bi] = cs;
        }
    }
}

// ---------------- K3: per-row log-prob (warp per row) + fused final loss ----------------
__global__ void __launch_bounds__(256) k_rowfix(const float* __restrict__ outm,
                                                float* __restrict__ out, int moff) {
    const int wid = threadIdx.x >> 5, lane = threadIdx.x & 31;
    const int i = blockIdx.x * 8 + wid;

    const float4 a = *(const float4*)(g_f + (size_t)i * D + lane * 4);

    auto dot = [&](int j) -> float {
        float4 b = *(const float4*)(g_f + (size_t)j * D + lane * 4);
        float p = a.x * b.x + a.y * b.y + a.z * b.z + a.w * b.w;
        #pragma unroll
        for (int o = 16; o; o >>= 1) p += __shfl_xor_sync(0xffffffffu, p, o);
        return p;
    };

    float simpos = (dot(i ^ BHALF) - 1.0f) * INV_T;

    int cnt = g_cnt[i];
    float corr = 0.0f;
    if (cnt <= 64) {
        for (int k = 0; k < cnt; k++) {
            int j = g_sidx[i * 64 + k];
            float m = g_sval[i * 64 + k];
            corr += m * __expf((dot(j) - 1.0f) * INV_T);
        }
    } else {
        for (int j = 0; j < N; j++) {
            float m = outm[(size_t)i * N + j];
            if (m > 0.0f) corr += m * __expf((dot(j) - 1.0f) * INV_T);
        }
    }

    float zp = g_partial[(size_t)i * 32 + lane];   // one coalesced 128B line per warp
    #pragma unroll
    for (int o = 16; o; o >>= 1) zp += __shfl_xor_sync(0xffffffffu, zp, o);

    if (lane == 0) g_lp[i] = simpos - logf(zp - corr);

    // ---- last-block loss reduction (threadFenceReduction pattern; deterministic order) ----
    __syncthreads();
    __shared__ bool isLast;
    if (threadIdx.x == 0) {
        __threadfence();
        int prev = atomicAdd(&g_done, 1);
        isLast = (prev == (int)gridDim.x - 1);
    }
    __syncthreads();
    if (isLast) {
        __shared__ float sm[8];
        float s = 0.0f;
        #pragma unroll
        for (int k = 0; k < 16; k++) s += g_lp[threadIdx.x + k * 256];
        #pragma unroll
        for (int o = 16; o; o >>= 1) s += __shfl_xor_sync(0xffffffffu, s, o);
        if (lane == 0) sm[wid] = s;
        __syncthreads();
        if (threadIdx.x == 0) {
            float tot = ((sm[0] + sm[1]) + (sm[2] + sm[3])) + ((sm[4] + sm[5]) + (sm[6] + sm[7]));
            float loss = -(tot / 4096.0f);
            for (int q = 0; q < moff; q++) out[q] = loss;
            g_done = 0;   // reset for next graph replay
        }
    }
}

// ---------------- launch ----------------
extern "C" void kernel_launch(void* const* d_in, const int* in_sizes, int n_in,
                              void* d_out, int out_size) {
    int fidx = (in_sizes[0] == N * D) ? 0 : 1;
    const float* feat = (const float*)d_in[fidx];
    const float* attn = (const float*)d_in[1 - fidx];
    float* out = (float*)d_out;

    long long nn = (long long)N * (long long)N;
    int moff = (int)((long long)out_size - nn);
    if (moff < 0) moff = 0;
    float* outm = out + moff;

    k_sparse<<<N, 512>>>(feat, attn, outm);
    k_gemm<<<528, 256>>>();
    k_rowfix<<<512, 256>>>(outm, out, moff);
}